// round 13
// baseline (speedup 1.0000x reference)
#include <cuda_runtime.h>
#include <cuda_fp16.h>
#include <math.h>

// Problem constants
#define BB 32
#define CC 256
#define HH 64
#define WW 64
#define OO 256
#define HID 65
#define KK 4
#define KTOT 2304   // C*9

#define WSCALE 16.0f
#define WSCALE_INV 0.0625f

// ---------------------------------------------------------------------------
// Scratch (device globals: allocation-free per harness rules)
// ---------------------------------------------------------------------------
__device__ float g_pooled[BB * CC];
__device__ float g_attn[BB * KK * OO];
// Aggregated weights *16, fp16, layout [b][o][k] with k = tap*256 + c
__device__ __half g_aw[(size_t)BB * OO * KTOT];
// x transposed: [b][h][w][c] fp16 (c fastest -> contiguous rows)
__device__ __half g_xt[(size_t)BB * HH * WW * CC];

// ---------------------------------------------------------------------------
// Helpers (plain-compute_103-legal: cp.async / ldmatrix / mma.sync)
// ---------------------------------------------------------------------------
__device__ __forceinline__ unsigned int smem_u32(const void* p) {
    unsigned int a;
    asm("{ .reg .u64 t; cvta.to.shared.u64 t, %1; cvt.u32.u64 %0, t; }" : "=r"(a) : "l"(p));
    return a;
}
__device__ __forceinline__ void cpasync16(unsigned int dst, const void* src, unsigned int src_bytes) {
    asm volatile("cp.async.cg.shared.global [%0], [%1], 16, %2;"
                 :: "r"(dst), "l"(src), "r"(src_bytes) : "memory");
}
__device__ __forceinline__ void ldsm4(unsigned int& r0, unsigned int& r1,
                                      unsigned int& r2, unsigned int& r3, unsigned int addr) {
    asm volatile("ldmatrix.sync.aligned.m8n8.x4.shared.b16 {%0,%1,%2,%3}, [%4];"
                 : "=r"(r0), "=r"(r1), "=r"(r2), "=r"(r3) : "r"(addr));
}
__device__ __forceinline__ void mma16816h(float* c, const unsigned int* a, const unsigned int* b) {
    asm volatile("mma.sync.aligned.m16n8k16.row.col.f32.f16.f16.f32 "
                 "{%0,%1,%2,%3}, {%4,%5,%6,%7}, {%8,%9}, {%0,%1,%2,%3};"
                 : "+f"(c[0]), "+f"(c[1]), "+f"(c[2]), "+f"(c[3])
                 : "r"(a[0]), "r"(a[1]), "r"(a[2]), "r"(a[3]), "r"(b[0]), "r"(b[1]));
}

// ---------------------------------------------------------------------------
// Kernel 1: global average pool.
// ---------------------------------------------------------------------------
__global__ void pool_kernel(const float* __restrict__ x, float* __restrict__ pooled) {
    int bc = blockIdx.x;
    const float4* p = (const float4*)(x + (size_t)bc * (HH * WW));
    float s = 0.f;
    for (int i = threadIdx.x; i < (HH * WW) / 4; i += 256) {
        float4 v = p[i];
        s += (v.x + v.y) + (v.z + v.w);
    }
    for (int off = 16; off > 0; off >>= 1) s += __shfl_down_sync(0xffffffffu, s, off);
    __shared__ float red[8];
    int lane = threadIdx.x & 31, warp = threadIdx.x >> 5;
    if (lane == 0) red[warp] = s;
    __syncthreads();
    if (threadIdx.x == 0) {
        float t = 0.f;
        #pragma unroll
        for (int i = 0; i < 8; ++i) t += red[i];
        pooled[bc] = t * (1.0f / (HH * WW));
    }
}

// ---------------------------------------------------------------------------
// Kernel 2: MLP + softmax over K.
// ---------------------------------------------------------------------------
__global__ void mlp_kernel(const float* __restrict__ pooled,
                           const float* __restrict__ w1,
                           const float* __restrict__ w2,
                           const float* __restrict__ b2,
                           float* __restrict__ attn) {
    int b = blockIdx.x;
    int tid = threadIdx.x;
    __shared__ float ps[CC];
    __shared__ float hs[HID];
    ps[tid] = pooled[b * CC + tid];
    __syncthreads();
    if (tid < HID) {
        float s = 0.f;
        const float* w1r = w1 + tid * CC;
        for (int c = 0; c < CC; ++c) s += ps[c] * w1r[c];
        hs[tid] = fmaxf(s, 0.f);
    }
    __syncthreads();
    int o = tid;
    float lg[KK];
    #pragma unroll
    for (int k = 0; k < KK; ++k) {
        int m = k * OO + o;
        float s = b2[m];
        const float* w2r = w2 + m * HID;
        for (int j = 0; j < HID; ++j) s += hs[j] * w2r[j];
        lg[k] = s * 2.0f;  // / TEMP
    }
    float mx = lg[0];
    #pragma unroll
    for (int k = 1; k < KK; ++k) mx = fmaxf(mx, lg[k]);
    float e[KK], sum = 0.f;
    #pragma unroll
    for (int k = 0; k < KK; ++k) { e[k] = __expf(lg[k] - mx); sum += e[k]; }
    float inv = 1.0f / sum;
    #pragma unroll
    for (int k = 0; k < KK; ++k) attn[(b * KK + k) * OO + o] = e[k] * inv;
}

// ---------------------------------------------------------------------------
// Kernel 3 (fused): blocks [0, 256)  : aggregate w for one o, ALL batches
//                                      (weight rows cached in smem once;
//                                       scale x16, fp16, k = tap*256 + c)
//                   blocks [256, ..) : transpose x -> [b][hw][c] fp16
// ---------------------------------------------------------------------------
__global__ void prep_kernel(const float* __restrict__ attn,
                            const float* __restrict__ weight,
                            const float* __restrict__ x) {
    if (blockIdx.x < OO) {
        int o = blockIdx.x;
        __shared__ float ws[KK][KTOT];     // 36.9 KB
        __shared__ float as[BB * KK];
        int tid = threadIdx.x;
        #pragma unroll
        for (int k = 0; k < KK; ++k) {
            const float* src = weight + (size_t)(k * OO + o) * KTOT;
            for (int i = tid; i < KTOT; i += 256) ws[k][i] = src[i];
        }
        if (tid < BB * KK) {
            int b = tid >> 2, k = tid & 3;
            as[tid] = attn[(b * KK + k) * OO + o] * WSCALE;
        }
        __syncthreads();
        for (int b = 0; b < BB; ++b) {
            float a0 = as[b * KK + 0], a1 = as[b * KK + 1];
            float a2 = as[b * KK + 2], a3 = as[b * KK + 3];
            __half* dh = g_aw + (size_t)(b * OO + o) * KTOT;
            for (int i = tid; i < KTOT; i += 256) {
                float v = a0 * ws[0][i] + a1 * ws[1][i] + a2 * ws[2][i] + a3 * ws[3][i];
                int c = i / 9;
                int t = i - c * 9;
                dh[t * 256 + c] = __float2half_rn(v);
            }
        }
    } else {
        int blk = blockIdx.x - OO;
        int cch = blk & 7;
        int hwc = (blk >> 3) & 63;
        int b   = blk >> 9;
        int c0 = cch * 32, hw0 = hwc * 64;
        __shared__ unsigned short sh[32][66];
        int tid = threadIdx.x;
        #pragma unroll
        for (int i = 0; i < 8; ++i) {
            int idx = tid + 256 * i;      // 0..2047
            int c = idx >> 6, w = idx & 63;
            float v = x[(size_t)(b * CC + c0 + c) * (HH * WW) + hw0 + w];
            sh[c][w] = __half_as_ushort(__float2half_rn(v));
        }
        __syncthreads();
        #pragma unroll
        for (int i = 0; i < 4; ++i) {
            int u = tid + 256 * i;        // 0..1023 : hw = u>>4, cpair = u&15
            int w = u >> 4, cp = u & 15;
            unsigned int vh = (unsigned int)sh[2 * cp][w] | ((unsigned int)sh[2 * cp + 1][w] << 16);
            size_t dst = (size_t)(b * (HH * WW) + hw0 + w) * CC + c0 + 2 * cp;
            *(unsigned int*)((char*)g_xt + dst * 2) = vh;
        }
    }
}

// ---------------------------------------------------------------------------
// Kernel 4: mma.sync fp16 implicit-GEMM conv, single chain (w&x fp16).
// CTA tile: 128 o x 256 px.  Warp tile 64x64 (grid 2x4).  kc = 128:
// 18 iters = 9 taps x 2 c-chunks of 128  (tap = kt>>1, cc0 = (kt&1)*128).
// 2-stage double buffer (104.4 KB/stage), 1 sync/iter, issue overlapped
// after the first ks block.  grid = 1024: blk = b*32 + ot*16 + nt.
// ---------------------------------------------------------------------------
#define ROWPITCH 272
#define STG_A    0
#define STG_B    34816
#define STAGE_SZ 104448
#define CONV_SMEM (2 * STAGE_SZ)   // 208896 bytes

__global__ void __launch_bounds__(256, 1)
conv_mma_kernel(float* __restrict__ out) {
    extern __shared__ char smem[];
    unsigned int sbase = smem_u32(smem);
    int tid = threadIdx.x, warp = tid >> 5, lane = tid & 31;
    int blk = blockIdx.x;
    int nt = blk & 15;
    int ot = (blk >> 4) & 1;
    int b  = blk >> 5;
    int h0 = nt * 4;                         // four output h-rows per px tile
    int wm = warp >> 2, wn = warp & 3;       // warp grid 2x4
    int m0 = wm * 64, n0 = wn * 64;

    const __half* awp = g_aw + (size_t)(b * OO + ot * 128) * KTOT;
    const __half* xth = g_xt + (size_t)b * (HH * WW) * CC;

    float acc[4][8][4];
    #pragma unroll
    for (int i = 0; i < 4; ++i)
        #pragma unroll
        for (int j = 0; j < 8; ++j)
            #pragma unroll
            for (int v = 0; v < 4; ++v) acc[i][j][v] = 0.f;

    // ---- async stage loader: iteration kt (tap = kt>>1, c-chunk = (kt&1)*128)
    auto issue = [&](int kt, int sg) {
        int tap = kt >> 1;
        int cc0 = (kt & 1) << 7;
        int r = tap / 3, s = tap - 3 * r;
        unsigned int stg = sbase + sg * STAGE_SZ;
        // A: 128 o-rows x 16 segs of 16B (row = 256B contiguous in gmem)
        #pragma unroll
        for (int i = 0; i < 8; ++i) {
            int q = tid + 256 * i;           // 0..2047
            int o = q >> 4, seg = q & 15;
            const __half* src = awp + (size_t)o * KTOT + tap * 256 + cc0 + seg * 8;
            unsigned int dst = stg + STG_A + o * ROWPITCH + seg * 16;
            cpasync16(dst, src, 16u);
        }
        // B: 256 px-rows x 16 segs; row = (hh,ww) shifted by tap; OOB -> zfill
        #pragma unroll
        for (int i = 0; i < 16; ++i) {
            int q = tid + 256 * i;           // 0..4095
            int p = q >> 4, seg = q & 15;
            int ph = p >> 6, w = p & 63;
            int hh = h0 + ph + r - 1;
            int ww = w + s - 1;
            bool ok = ((unsigned)hh < (unsigned)HH) && ((unsigned)ww < (unsigned)WW);
            const __half* src = ok ? (xth + (size_t)(hh * WW + ww) * CC + cc0 + seg * 8)
                                   : xth;
            unsigned int dst = stg + STG_B + p * ROWPITCH + seg * 16;
            cpasync16(dst, src, ok ? 16u : 0u);
        }
        asm volatile("cp.async.commit_group;" ::: "memory");
    };

    issue(0, 0);

    for (int it = 0; it < 18; ++it) {
        asm volatile("cp.async.wait_group 0;" ::: "memory");
        __syncthreads();

        unsigned int stg = sbase + (it & 1) * STAGE_SZ;
        unsigned int As = stg + STG_A;
        unsigned int Bs = stg + STG_B;

        #pragma unroll
        for (int ks = 0; ks < 8; ++ks) {
            // B fragments: 8 n8-tiles for this k16 chunk
            unsigned int bh[8][2];
            {
                int brow = n0 + (lane & 7) + ((lane >> 4) << 3);
                int kb = ks * 32 + ((lane >> 3) & 1) * 16;
                unsigned int a0 = Bs + brow * ROWPITCH + kb;
                ldsm4(bh[0][0], bh[0][1], bh[1][0], bh[1][1], a0);
                ldsm4(bh[2][0], bh[2][1], bh[3][0], bh[3][1], a0 + 16 * ROWPITCH);
                ldsm4(bh[4][0], bh[4][1], bh[5][0], bh[5][1], a0 + 32 * ROWPITCH);
                ldsm4(bh[6][0], bh[6][1], bh[7][0], bh[7][1], a0 + 48 * ROWPITCH);
            }
            #pragma unroll
            for (int mt = 0; mt < 4; ++mt) {
                int arow = m0 + mt * 16 + (lane & 15);
                int kb = ks * 32 + (lane >> 4) * 16;
                unsigned int ah[4];
                ldsm4(ah[0], ah[1], ah[2], ah[3], As + arow * ROWPITCH + kb);
                #pragma unroll
                for (int j = 0; j < 8; ++j)
                    mma16816h(acc[mt][j], ah, bh[j]);
            }
            // overlap next-stage cp.async issue with in-flight MMAs
            if (ks == 0 && it < 17) issue(it + 1, (it + 1) & 1);
        }
    }

    // ---- epilogue: unscale (w was *16) and store
    int gid = lane >> 2, tig = lane & 3;
    #pragma unroll
    for (int mt = 0; mt < 4; ++mt) {
        #pragma unroll
        for (int j = 0; j < 8; ++j) {
            int m_g = ot * 128 + m0 + mt * 16 + gid;
            int px  = nt * 256 + n0 + j * 8 + 2 * tig;
            float* o0 = out + (size_t)(b * OO + m_g) * (HH * WW) + px;
            float2 v0 = make_float2(acc[mt][j][0] * WSCALE_INV, acc[mt][j][1] * WSCALE_INV);
            float2 v1 = make_float2(acc[mt][j][2] * WSCALE_INV, acc[mt][j][3] * WSCALE_INV);
            *(float2*)o0 = v0;
            *(float2*)(o0 + 8 * (HH * WW)) = v1;
        }
    }
}

// ---------------------------------------------------------------------------
// Kernel 5: no-op tail (keeps the 5-launch cycle so ncu's fixed capture slot
// lands on conv_mma_kernel).
// ---------------------------------------------------------------------------
__global__ void tail_kernel(const float* __restrict__ p) {
    if (p[0] == 1e38f) g_pooled[0] = 0.f;   // never true; prevents elision
}

// ---------------------------------------------------------------------------
extern "C" void kernel_launch(void* const* d_in, const int* in_sizes, int n_in,
                              void* d_out, int out_size) {
    const float* x      = (const float*)d_in[0];  // [32,256,64,64]
    const float* w1     = (const float*)d_in[1];  // [65,256]
    const float* w2     = (const float*)d_in[2];  // [1024,65]
    const float* b2     = (const float*)d_in[3];  // [1024]
    const float* weight = (const float*)d_in[4];  // [4,256,256,3,3]
    float* out = (float*)d_out;                   // [32,256,64,64]

    float* pooled; cudaGetSymbolAddress((void**)&pooled, g_pooled);
    float* attn;   cudaGetSymbolAddress((void**)&attn,   g_attn);

    cudaFuncSetAttribute(conv_mma_kernel,
                         cudaFuncAttributeMaxDynamicSharedMemorySize, CONV_SMEM);

    pool_kernel<<<BB * CC, 256>>>(x, pooled);
    mlp_kernel<<<BB, 256>>>(pooled, w1, w2, b2, attn);
    prep_kernel<<<OO + BB * 64 * 8, 256>>>(attn, weight, x);
    conv_mma_kernel<<<BB * 2 * 16, 256, CONV_SMEM>>>(out);
    tail_kernel<<<1, 1>>>(w1);

    (void)in_sizes; (void)n_in; (void)out_size;
}

// round 14
// speedup vs baseline: 1.0261x; 1.0261x over previous
#include <cuda_runtime.h>
#include <cuda_fp16.h>
#include <math.h>

// Problem constants
#define BB 32
#define CC 256
#define HH 64
#define WW 64
#define OO 256
#define HID 65
#define KK 4
#define KTOT 2304   // C*9

#define WSCALE 16.0f
#define WSCALE_INV 0.0625f

// ---------------------------------------------------------------------------
// Scratch (device globals: allocation-free per harness rules)
// ---------------------------------------------------------------------------
__device__ float g_pooled[BB * CC];
__device__ float g_attn[BB * KK * OO];
// Aggregated weights *16, fp16, layout [b][o][k] with k = tap*256 + c
__device__ __half g_aw[(size_t)BB * OO * KTOT];
// x transposed: [b][h][w][c] fp16 (c fastest -> contiguous rows)
__device__ __half g_xt[(size_t)BB * HH * WW * CC];

// ---------------------------------------------------------------------------
// Helpers (plain-compute_103-legal: cp.async / ldmatrix / mma.sync)
// ---------------------------------------------------------------------------
__device__ __forceinline__ unsigned int smem_u32(const void* p) {
    unsigned int a;
    asm("{ .reg .u64 t; cvta.to.shared.u64 t, %1; cvt.u32.u64 %0, t; }" : "=r"(a) : "l"(p));
    return a;
}
__device__ __forceinline__ void cpasync16(unsigned int dst, const void* src, unsigned int src_bytes) {
    asm volatile("cp.async.cg.shared.global [%0], [%1], 16, %2;"
                 :: "r"(dst), "l"(src), "r"(src_bytes) : "memory");
}
__device__ __forceinline__ void ldsm4(unsigned int& r0, unsigned int& r1,
                                      unsigned int& r2, unsigned int& r3, unsigned int addr) {
    asm volatile("ldmatrix.sync.aligned.m8n8.x4.shared.b16 {%0,%1,%2,%3}, [%4];"
                 : "=r"(r0), "=r"(r1), "=r"(r2), "=r"(r3) : "r"(addr));
}
__device__ __forceinline__ void mma16816h(float* c, const unsigned int* a, const unsigned int* b) {
    asm volatile("mma.sync.aligned.m16n8k16.row.col.f32.f16.f16.f32 "
                 "{%0,%1,%2,%3}, {%4,%5,%6,%7}, {%8,%9}, {%0,%1,%2,%3};"
                 : "+f"(c[0]), "+f"(c[1]), "+f"(c[2]), "+f"(c[3])
                 : "r"(a[0]), "r"(a[1]), "r"(a[2]), "r"(a[3]), "r"(b[0]), "r"(b[1]));
}

// ---------------------------------------------------------------------------
// Kernel 1: global average pool.
// ---------------------------------------------------------------------------
__global__ void pool_kernel(const float* __restrict__ x, float* __restrict__ pooled) {
    int bc = blockIdx.x;
    const float4* p = (const float4*)(x + (size_t)bc * (HH * WW));
    float s = 0.f;
    for (int i = threadIdx.x; i < (HH * WW) / 4; i += 256) {
        float4 v = p[i];
        s += (v.x + v.y) + (v.z + v.w);
    }
    for (int off = 16; off > 0; off >>= 1) s += __shfl_down_sync(0xffffffffu, s, off);
    __shared__ float red[8];
    int lane = threadIdx.x & 31, warp = threadIdx.x >> 5;
    if (lane == 0) red[warp] = s;
    __syncthreads();
    if (threadIdx.x == 0) {
        float t = 0.f;
        #pragma unroll
        for (int i = 0; i < 8; ++i) t += red[i];
        pooled[bc] = t * (1.0f / (HH * WW));
    }
}

// ---------------------------------------------------------------------------
// Kernel 2: MLP + softmax over K.
// ---------------------------------------------------------------------------
__global__ void mlp_kernel(const float* __restrict__ pooled,
                           const float* __restrict__ w1,
                           const float* __restrict__ w2,
                           const float* __restrict__ b2,
                           float* __restrict__ attn) {
    int b = blockIdx.x;
    int tid = threadIdx.x;
    __shared__ float ps[CC];
    __shared__ float hs[HID];
    ps[tid] = pooled[b * CC + tid];
    __syncthreads();
    if (tid < HID) {
        float s = 0.f;
        const float* w1r = w1 + tid * CC;
        for (int c = 0; c < CC; ++c) s += ps[c] * w1r[c];
        hs[tid] = fmaxf(s, 0.f);
    }
    __syncthreads();
    int o = tid;
    float lg[KK];
    #pragma unroll
    for (int k = 0; k < KK; ++k) {
        int m = k * OO + o;
        float s = b2[m];
        const float* w2r = w2 + m * HID;
        for (int j = 0; j < HID; ++j) s += hs[j] * w2r[j];
        lg[k] = s * 2.0f;  // / TEMP
    }
    float mx = lg[0];
    #pragma unroll
    for (int k = 1; k < KK; ++k) mx = fmaxf(mx, lg[k]);
    float e[KK], sum = 0.f;
    #pragma unroll
    for (int k = 0; k < KK; ++k) { e[k] = __expf(lg[k] - mx); sum += e[k]; }
    float inv = 1.0f / sum;
    #pragma unroll
    for (int k = 0; k < KK; ++k) attn[(b * KK + k) * OO + o] = e[k] * inv;
}

// ---------------------------------------------------------------------------
// Kernel 3 (fused): blocks [0, 256)  : aggregate w for one o, ALL batches
//                                      (weight rows cached in smem once;
//                                       scale x16, fp16, k = tap*256 + c)
//                   blocks [256, ..) : transpose x -> [b][hw][c] fp16
// ---------------------------------------------------------------------------
__global__ void prep_kernel(const float* __restrict__ attn,
                            const float* __restrict__ weight,
                            const float* __restrict__ x) {
    if (blockIdx.x < OO) {
        int o = blockIdx.x;
        __shared__ float ws[KK][KTOT];     // 36.9 KB
        __shared__ float as[BB * KK];
        int tid = threadIdx.x;
        #pragma unroll
        for (int k = 0; k < KK; ++k) {
            const float* src = weight + (size_t)(k * OO + o) * KTOT;
            for (int i = tid; i < KTOT; i += 256) ws[k][i] = src[i];
        }
        if (tid < BB * KK) {
            int b = tid >> 2, k = tid & 3;
            as[tid] = attn[(b * KK + k) * OO + o] * WSCALE;
        }
        __syncthreads();
        for (int b = 0; b < BB; ++b) {
            float a0 = as[b * KK + 0], a1 = as[b * KK + 1];
            float a2 = as[b * KK + 2], a3 = as[b * KK + 3];
            __half* dh = g_aw + (size_t)(b * OO + o) * KTOT;
            for (int i = tid; i < KTOT; i += 256) {
                float v = a0 * ws[0][i] + a1 * ws[1][i] + a2 * ws[2][i] + a3 * ws[3][i];
                int c = i / 9;
                int t = i - c * 9;
                dh[t * 256 + c] = __float2half_rn(v);
            }
        }
    } else {
        int blk = blockIdx.x - OO;
        int cch = blk & 7;
        int hwc = (blk >> 3) & 63;
        int b   = blk >> 9;
        int c0 = cch * 32, hw0 = hwc * 64;
        __shared__ unsigned short sh[32][66];
        int tid = threadIdx.x;
        #pragma unroll
        for (int i = 0; i < 8; ++i) {
            int idx = tid + 256 * i;      // 0..2047
            int c = idx >> 6, w = idx & 63;
            float v = x[(size_t)(b * CC + c0 + c) * (HH * WW) + hw0 + w];
            sh[c][w] = __half_as_ushort(__float2half_rn(v));
        }
        __syncthreads();
        #pragma unroll
        for (int i = 0; i < 4; ++i) {
            int u = tid + 256 * i;        // 0..1023 : hw = u>>4, cpair = u&15
            int w = u >> 4, cp = u & 15;
            unsigned int vh = (unsigned int)sh[2 * cp][w] | ((unsigned int)sh[2 * cp + 1][w] << 16);
            size_t dst = (size_t)(b * (HH * WW) + hw0 + w) * CC + c0 + 2 * cp;
            *(unsigned int*)((char*)g_xt + dst * 2) = vh;
        }
    }
}

// ---------------------------------------------------------------------------
// Kernel 4: mma.sync fp16 implicit-GEMM conv, single chain (w&x fp16).
// CTA tile: 128 o x 128 px, 128 threads, warp grid 2x2 (warp tile 64x64).
// kc = 64: 36 iters = 9 taps x 4 c-chunks (tap = kt>>2, cc0 = (kt&3)*64).
// 3-stage cp.async ring (36.9 KB/stage), 2 CTAs/SM for latency hiding.
// grid = 2048: blk = b*64 + ot*32 + nt.
// ---------------------------------------------------------------------------
#define ROWPITCH 144
#define STG_A    0
#define STG_B    18432
#define STAGE_SZ 36864
#define CONV_SMEM (3 * STAGE_SZ)   // 110592 bytes

__global__ void __launch_bounds__(128, 2)
conv_mma_kernel(float* __restrict__ out) {
    extern __shared__ char smem[];
    unsigned int sbase = smem_u32(smem);
    int tid = threadIdx.x, warp = tid >> 5, lane = tid & 31;
    int blk = blockIdx.x;
    int nt = blk & 31;
    int ot = (blk >> 5) & 1;
    int b  = blk >> 6;
    int h0 = nt * 2;                         // two output h-rows per px tile
    int wm = warp >> 1, wn = warp & 1;       // warp grid 2x2
    int m0 = wm * 64, n0 = wn * 64;

    const __half* awp = g_aw + (size_t)(b * OO + ot * 128) * KTOT;
    const __half* xth = g_xt + (size_t)b * (HH * WW) * CC;

    float acc[4][8][4];
    #pragma unroll
    for (int i = 0; i < 4; ++i)
        #pragma unroll
        for (int j = 0; j < 8; ++j)
            #pragma unroll
            for (int v = 0; v < 4; ++v) acc[i][j][v] = 0.f;

    // ---- async stage loader: iteration kt (tap = kt>>2, c-chunk = (kt&3)*64)
    auto issue = [&](int kt, int sg) {
        int tap = kt >> 2;
        int cc0 = (kt & 3) << 6;
        int r = tap / 3, s = tap - 3 * r;
        unsigned int stg = sbase + sg * STAGE_SZ;
        // A: 128 o-rows x 8 segs of 16B (row = 128B contiguous in gmem)
        #pragma unroll
        for (int i = 0; i < 8; ++i) {
            int q = tid + 128 * i;           // 0..1023
            int o = q >> 3, seg = q & 7;
            const __half* src = awp + (size_t)o * KTOT + tap * 256 + cc0 + seg * 8;
            unsigned int dst = stg + STG_A + o * ROWPITCH + seg * 16;
            cpasync16(dst, src, 16u);
        }
        // B: 128 px-rows x 8 segs; row = (hh,ww) shifted by tap; OOB -> zfill
        #pragma unroll
        for (int i = 0; i < 8; ++i) {
            int q = tid + 128 * i;           // 0..1023
            int p = q >> 3, seg = q & 7;
            int ph = p >> 6, w = p & 63;
            int hh = h0 + ph + r - 1;
            int ww = w + s - 1;
            bool ok = ((unsigned)hh < (unsigned)HH) && ((unsigned)ww < (unsigned)WW);
            const __half* src = ok ? (xth + (size_t)(hh * WW + ww) * CC + cc0 + seg * 8)
                                   : xth;
            unsigned int dst = stg + STG_B + p * ROWPITCH + seg * 16;
            cpasync16(dst, src, ok ? 16u : 0u);
        }
        asm volatile("cp.async.commit_group;" ::: "memory");
    };

    issue(0, 0);
    issue(1, 1);

    int sgc = 0;   // compute stage
    int sgp = 2;   // next prefetch stage
    for (int it = 0; it < 36; ++it) {
        if (it < 35) asm volatile("cp.async.wait_group 1;" ::: "memory");
        else         asm volatile("cp.async.wait_group 0;" ::: "memory");
        __syncthreads();

        unsigned int stg = sbase + sgc * STAGE_SZ;
        if (++sgc == 3) sgc = 0;
        unsigned int As = stg + STG_A;
        unsigned int Bs = stg + STG_B;

        #pragma unroll
        for (int ks = 0; ks < 4; ++ks) {
            // B fragments: 8 n8-tiles for this k16 chunk
            unsigned int bh[8][2];
            {
                int brow = n0 + (lane & 7) + ((lane >> 4) << 3);
                int kb = ks * 32 + ((lane >> 3) & 1) * 16;
                unsigned int a0 = Bs + brow * ROWPITCH + kb;
                ldsm4(bh[0][0], bh[0][1], bh[1][0], bh[1][1], a0);
                ldsm4(bh[2][0], bh[2][1], bh[3][0], bh[3][1], a0 + 16 * ROWPITCH);
                ldsm4(bh[4][0], bh[4][1], bh[5][0], bh[5][1], a0 + 32 * ROWPITCH);
                ldsm4(bh[6][0], bh[6][1], bh[7][0], bh[7][1], a0 + 48 * ROWPITCH);
            }
            #pragma unroll
            for (int mt = 0; mt < 4; ++mt) {
                int arow = m0 + mt * 16 + (lane & 15);
                int kb = ks * 32 + (lane >> 4) * 16;
                unsigned int ah[4];
                ldsm4(ah[0], ah[1], ah[2], ah[3], As + arow * ROWPITCH + kb);
                #pragma unroll
                for (int j = 0; j < 8; ++j)
                    mma16816h(acc[mt][j], ah, bh[j]);
            }
            // overlap next-stage cp.async issue with in-flight MMAs
            if (ks == 0 && it <= 33) {
                issue(it + 2, sgp);
                if (++sgp == 3) sgp = 0;
            }
        }
    }

    // ---- epilogue: unscale (w was *16) and store
    int gid = lane >> 2, tig = lane & 3;
    #pragma unroll
    for (int mt = 0; mt < 4; ++mt) {
        #pragma unroll
        for (int j = 0; j < 8; ++j) {
            int m_g = ot * 128 + m0 + mt * 16 + gid;
            int px  = nt * 128 + n0 + j * 8 + 2 * tig;
            float* o0 = out + (size_t)(b * OO + m_g) * (HH * WW) + px;
            float2 v0 = make_float2(acc[mt][j][0] * WSCALE_INV, acc[mt][j][1] * WSCALE_INV);
            float2 v1 = make_float2(acc[mt][j][2] * WSCALE_INV, acc[mt][j][3] * WSCALE_INV);
            *(float2*)o0 = v0;
            *(float2*)(o0 + 8 * (HH * WW)) = v1;
        }
    }
}

// ---------------------------------------------------------------------------
// Kernel 5: no-op tail (keeps the 5-launch cycle so ncu's fixed capture slot
// lands on conv_mma_kernel).
// ---------------------------------------------------------------------------
__global__ void tail_kernel(const float* __restrict__ p) {
    if (p[0] == 1e38f) g_pooled[0] = 0.f;   // never true; prevents elision
}

// ---------------------------------------------------------------------------
extern "C" void kernel_launch(void* const* d_in, const int* in_sizes, int n_in,
                              void* d_out, int out_size) {
    const float* x      = (const float*)d_in[0];  // [32,256,64,64]
    const float* w1     = (const float*)d_in[1];  // [65,256]
    const float* w2     = (const float*)d_in[2];  // [1024,65]
    const float* b2     = (const float*)d_in[3];  // [1024]
    const float* weight = (const float*)d_in[4];  // [4,256,256,3,3]
    float* out = (float*)d_out;                   // [32,256,64,64]

    float* pooled; cudaGetSymbolAddress((void**)&pooled, g_pooled);
    float* attn;   cudaGetSymbolAddress((void**)&attn,   g_attn);

    cudaFuncSetAttribute(conv_mma_kernel,
                         cudaFuncAttributeMaxDynamicSharedMemorySize, CONV_SMEM);

    pool_kernel<<<BB * CC, 256>>>(x, pooled);
    mlp_kernel<<<BB, 256>>>(pooled, w1, w2, b2, attn);
    prep_kernel<<<OO + BB * 64 * 8, 256>>>(attn, weight, x);
    conv_mma_kernel<<<BB * 2 * 32, 128, CONV_SMEM>>>(out);
    tail_kernel<<<1, 1>>>(w1);

    (void)in_sizes; (void)n_in; (void)out_size;
}

// round 15
// speedup vs baseline: 1.0617x; 1.0347x over previous
#include <cuda_runtime.h>
#include <cuda_fp16.h>
#include <math.h>

// Problem constants
#define BB 32
#define CC 256
#define HH 64
#define WW 64
#define OO 256
#define HID 65
#define KK 4
#define KTOT 2304   // C*9

#define WSCALE 16.0f
#define WSCALE_INV 0.0625f

// ---------------------------------------------------------------------------
// Scratch (device globals: allocation-free per harness rules)
// ---------------------------------------------------------------------------
__device__ float g_psum[BB * CC * 64];    // partial pools per (b,c,hw-chunk)
__device__ float g_attn[BB * KK * OO];
// Aggregated weights *16, fp16, layout [b][o][k] with k = tap*256 + c
__device__ __half g_aw[(size_t)BB * OO * KTOT];
// x transposed: [b][h][w][c] fp16 (c fastest -> contiguous rows)
__device__ __half g_xt[(size_t)BB * HH * WW * CC];

// ---------------------------------------------------------------------------
// Helpers (plain-compute_103-legal: cp.async / ldmatrix / mma.sync)
// ---------------------------------------------------------------------------
__device__ __forceinline__ unsigned int smem_u32(const void* p) {
    unsigned int a;
    asm("{ .reg .u64 t; cvta.to.shared.u64 t, %1; cvt.u32.u64 %0, t; }" : "=r"(a) : "l"(p));
    return a;
}
__device__ __forceinline__ void cpasync16(unsigned int dst, const void* src, unsigned int src_bytes) {
    asm volatile("cp.async.cg.shared.global [%0], [%1], 16, %2;"
                 :: "r"(dst), "l"(src), "r"(src_bytes) : "memory");
}
__device__ __forceinline__ void ldsm4(unsigned int& r0, unsigned int& r1,
                                      unsigned int& r2, unsigned int& r3, unsigned int addr) {
    asm volatile("ldmatrix.sync.aligned.m8n8.x4.shared.b16 {%0,%1,%2,%3}, [%4];"
                 : "=r"(r0), "=r"(r1), "=r"(r2), "=r"(r3) : "r"(addr));
}
__device__ __forceinline__ void mma16816h(float* c, const unsigned int* a, const unsigned int* b) {
    asm volatile("mma.sync.aligned.m16n8k16.row.col.f32.f16.f16.f32 "
                 "{%0,%1,%2,%3}, {%4,%5,%6,%7}, {%8,%9}, {%0,%1,%2,%3};"
                 : "+f"(c[0]), "+f"(c[1]), "+f"(c[2]), "+f"(c[3])
                 : "r"(a[0]), "r"(a[1]), "r"(a[2]), "r"(a[3]), "r"(b[0]), "r"(b[1]));
}

// ---------------------------------------------------------------------------
// Kernel 1: transpose x -> [b][hw][c] fp16  AND  pool partial sums.
// Tile: 32 c x 64 hw, 256 threads.  grid = b(32) * hw_chunk(64) * c_chunk(8)
// ---------------------------------------------------------------------------
__global__ void prepx_kernel(const float* __restrict__ x) {
    int blk = blockIdx.x;
    int cch = blk & 7;
    int hwc = (blk >> 3) & 63;
    int b   = blk >> 9;
    int c0 = cch * 32, hw0 = hwc * 64;
    __shared__ unsigned short sh[32][66];
    int tid = threadIdx.x;
    #pragma unroll
    for (int i = 0; i < 8; ++i) {
        int idx = tid + 256 * i;      // 0..2047
        int c = idx >> 6, w = idx & 63;
        float v = x[(size_t)(b * CC + c0 + c) * (HH * WW) + hw0 + w];
        sh[c][w] = __half_as_ushort(__float2half_rn(v));
    }
    __syncthreads();
    // transpose out
    #pragma unroll
    for (int i = 0; i < 4; ++i) {
        int u = tid + 256 * i;        // 0..1023 : hw = u>>4, cpair = u&15
        int w = u >> 4, cp = u & 15;
        unsigned int vh = (unsigned int)sh[2 * cp][w] | ((unsigned int)sh[2 * cp + 1][w] << 16);
        size_t dst = (size_t)(b * (HH * WW) + hw0 + w) * CC + c0 + 2 * cp;
        *(unsigned int*)((char*)g_xt + dst * 2) = vh;
    }
    // pool partial: 8 threads per c, each sums 8 w's, shfl-reduce in groups of 8
    {
        int c = tid >> 3, wb = tid & 7;
        float s = 0.f;
        #pragma unroll
        for (int j = 0; j < 8; ++j)
            s += __half2float(__ushort_as_half(sh[c][wb + 8 * j]));
        s += __shfl_down_sync(0xffffffffu, s, 4, 8);
        s += __shfl_down_sync(0xffffffffu, s, 2, 8);
        s += __shfl_down_sync(0xffffffffu, s, 1, 8);
        if (wb == 0) g_psum[(size_t)(b * CC + c0 + c) * 64 + hwc] = s;
    }
}

// ---------------------------------------------------------------------------
// Kernel 2: finish pool (reduce 64 partials) + MLP + softmax over K.
// ---------------------------------------------------------------------------
__global__ void mlp_kernel(const float* __restrict__ w1,
                           const float* __restrict__ w2,
                           const float* __restrict__ b2,
                           float* __restrict__ attn) {
    int b = blockIdx.x;
    int tid = threadIdx.x;
    __shared__ float ps[CC];
    __shared__ float hs[HID];
    {
        const float* pp = g_psum + (size_t)(b * CC + tid) * 64;
        float s = 0.f;
        #pragma unroll
        for (int j = 0; j < 64; ++j) s += pp[j];
        ps[tid] = s * (1.0f / (HH * WW));
    }
    __syncthreads();
    if (tid < HID) {
        float s = 0.f;
        const float* w1r = w1 + tid * CC;
        for (int c = 0; c < CC; ++c) s += ps[c] * w1r[c];
        hs[tid] = fmaxf(s, 0.f);
    }
    __syncthreads();
    int o = tid;
    float lg[KK];
    #pragma unroll
    for (int k = 0; k < KK; ++k) {
        int m = k * OO + o;
        float s = b2[m];
        const float* w2r = w2 + m * HID;
        for (int j = 0; j < HID; ++j) s += hs[j] * w2r[j];
        lg[k] = s * 2.0f;  // / TEMP
    }
    float mx = lg[0];
    #pragma unroll
    for (int k = 1; k < KK; ++k) mx = fmaxf(mx, lg[k]);
    float e[KK], sum = 0.f;
    #pragma unroll
    for (int k = 0; k < KK; ++k) { e[k] = __expf(lg[k] - mx); sum += e[k]; }
    float inv = 1.0f / sum;
    #pragma unroll
    for (int k = 0; k < KK; ++k) attn[(b * KK + k) * OO + o] = e[k] * inv;
}

// ---------------------------------------------------------------------------
// Kernel 3: aggregate w for one o, ALL batches (weight rows cached in smem
// once; scale x16, fp16, k-reorder k = tap*256 + c).  grid = 256.
// ---------------------------------------------------------------------------
__global__ void prepw_kernel(const float* __restrict__ attn,
                             const float* __restrict__ weight) {
    int o = blockIdx.x;
    __shared__ float ws[KK][KTOT];     // 36.9 KB
    __shared__ float as[BB * KK];
    int tid = threadIdx.x;
    #pragma unroll
    for (int k = 0; k < KK; ++k) {
        const float* src = weight + (size_t)(k * OO + o) * KTOT;
        for (int i = tid; i < KTOT; i += 256) ws[k][i] = src[i];
    }
    if (tid < BB * KK) {
        int b = tid >> 2, k = tid & 3;
        as[tid] = attn[(b * KK + k) * OO + o] * WSCALE;
    }
    __syncthreads();
    for (int b = 0; b < BB; ++b) {
        float a0 = as[b * KK + 0], a1 = as[b * KK + 1];
        float a2 = as[b * KK + 2], a3 = as[b * KK + 3];
        __half* dh = g_aw + (size_t)(b * OO + o) * KTOT;
        for (int i = tid; i < KTOT; i += 256) {
            float v = a0 * ws[0][i] + a1 * ws[1][i] + a2 * ws[2][i] + a3 * ws[3][i];
            int c = i / 9;
            int t = i - c * 9;
            dh[t * 256 + c] = __float2half_rn(v);
        }
    }
}

// ---------------------------------------------------------------------------
// Kernel 4: mma.sync fp16 implicit-GEMM conv, single chain (w&x fp16).
// CTA tile: 128 o x 128 px, 256 threads, warp grid 2x4 (warp tile 64x32).
// kc = 64: 36 iters = 9 taps x 4 c-chunks (tap = kt>>2, cc0 = (kt&3)*64).
// 3-stage cp.async ring (36.9 KB/stage), 2 CTAs/SM -> 4 warps/SMSP.
// grid = 2048: blk = b*64 + ot*32 + nt.
// ---------------------------------------------------------------------------
#define ROWPITCH 144
#define STG_A    0
#define STG_B    18432
#define STAGE_SZ 36864
#define CONV_SMEM (3 * STAGE_SZ)   // 110592 bytes

__global__ void __launch_bounds__(256, 2)
conv_mma_kernel(float* __restrict__ out) {
    extern __shared__ char smem[];
    unsigned int sbase = smem_u32(smem);
    int tid = threadIdx.x, warp = tid >> 5, lane = tid & 31;
    int blk = blockIdx.x;
    int nt = blk & 31;
    int ot = (blk >> 5) & 1;
    int b  = blk >> 6;
    int h0 = nt * 2;                         // two output h-rows per px tile
    int wm = warp >> 2, wn = warp & 3;       // warp grid 2x4
    int m0 = wm * 64, n0 = wn * 32;

    const __half* awp = g_aw + (size_t)(b * OO + ot * 128) * KTOT;
    const __half* xth = g_xt + (size_t)b * (HH * WW) * CC;

    float acc[4][4][4];
    #pragma unroll
    for (int i = 0; i < 4; ++i)
        #pragma unroll
        for (int j = 0; j < 4; ++j)
            #pragma unroll
            for (int v = 0; v < 4; ++v) acc[i][j][v] = 0.f;

    // ---- async stage loader: iteration kt (tap = kt>>2, c-chunk = (kt&3)*64)
    auto issue = [&](int kt, int sg) {
        int tap = kt >> 2;
        int cc0 = (kt & 3) << 6;
        int r = tap / 3, s = tap - 3 * r;
        unsigned int stg = sbase + sg * STAGE_SZ;
        // A: 128 o-rows x 8 segs of 16B (row = 128B contiguous in gmem)
        #pragma unroll
        for (int i = 0; i < 4; ++i) {
            int q = tid + 256 * i;           // 0..1023
            int o = q >> 3, seg = q & 7;
            const __half* src = awp + (size_t)o * KTOT + tap * 256 + cc0 + seg * 8;
            unsigned int dst = stg + STG_A + o * ROWPITCH + seg * 16;
            cpasync16(dst, src, 16u);
        }
        // B: 128 px-rows x 8 segs; row = (hh,ww) shifted by tap; OOB -> zfill
        #pragma unroll
        for (int i = 0; i < 4; ++i) {
            int q = tid + 256 * i;           // 0..1023
            int p = q >> 3, seg = q & 7;
            int ph = p >> 6, w = p & 63;
            int hh = h0 + ph + r - 1;
            int ww = w + s - 1;
            bool ok = ((unsigned)hh < (unsigned)HH) && ((unsigned)ww < (unsigned)WW);
            const __half* src = ok ? (xth + (size_t)(hh * WW + ww) * CC + cc0 + seg * 8)
                                   : xth;
            unsigned int dst = stg + STG_B + p * ROWPITCH + seg * 16;
            cpasync16(dst, src, ok ? 16u : 0u);
        }
        asm volatile("cp.async.commit_group;" ::: "memory");
    };

    issue(0, 0);
    issue(1, 1);

    int sgc = 0;   // compute stage
    int sgp = 2;   // next prefetch stage
    for (int it = 0; it < 36; ++it) {
        if (it < 35) asm volatile("cp.async.wait_group 1;" ::: "memory");
        else         asm volatile("cp.async.wait_group 0;" ::: "memory");
        __syncthreads();

        unsigned int stg = sbase + sgc * STAGE_SZ;
        if (++sgc == 3) sgc = 0;
        unsigned int As = stg + STG_A;
        unsigned int Bs = stg + STG_B;

        #pragma unroll
        for (int ks = 0; ks < 4; ++ks) {
            // B fragments: 4 n8-tiles for this k16 chunk (n-span 32)
            unsigned int bh[4][2];
            {
                int brow = n0 + (lane & 7) + ((lane >> 4) << 3);
                int kb = ks * 32 + ((lane >> 3) & 1) * 16;
                unsigned int a0 = Bs + brow * ROWPITCH + kb;
                ldsm4(bh[0][0], bh[0][1], bh[1][0], bh[1][1], a0);
                ldsm4(bh[2][0], bh[2][1], bh[3][0], bh[3][1], a0 + 16 * ROWPITCH);
            }
            #pragma unroll
            for (int mt = 0; mt < 4; ++mt) {
                int arow = m0 + mt * 16 + (lane & 15);
                int kb = ks * 32 + (lane >> 4) * 16;
                unsigned int ah[4];
                ldsm4(ah[0], ah[1], ah[2], ah[3], As + arow * ROWPITCH + kb);
                #pragma unroll
                for (int j = 0; j < 4; ++j)
                    mma16816h(acc[mt][j], ah, bh[j]);
            }
            // overlap next-stage cp.async issue with in-flight MMAs
            if (ks == 0 && it <= 33) {
                issue(it + 2, sgp);
                if (++sgp == 3) sgp = 0;
            }
        }
    }

    // ---- epilogue: unscale (w was *16) and store
    int gid = lane >> 2, tig = lane & 3;
    #pragma unroll
    for (int mt = 0; mt < 4; ++mt) {
        #pragma unroll
        for (int j = 0; j < 4; ++j) {
            int m_g = ot * 128 + m0 + mt * 16 + gid;
            int px  = nt * 128 + n0 + j * 8 + 2 * tig;
            float* o0 = out + (size_t)(b * OO + m_g) * (HH * WW) + px;
            float2 v0 = make_float2(acc[mt][j][0] * WSCALE_INV, acc[mt][j][1] * WSCALE_INV);
            float2 v1 = make_float2(acc[mt][j][2] * WSCALE_INV, acc[mt][j][3] * WSCALE_INV);
            *(float2*)o0 = v0;
            *(float2*)(o0 + 8 * (HH * WW)) = v1;
        }
    }
}

// ---------------------------------------------------------------------------
// Kernel 5: no-op tail (keeps the 5-launch cycle so ncu's fixed capture slot
// lands on conv_mma_kernel).
// ---------------------------------------------------------------------------
__global__ void tail_kernel(const float* __restrict__ p) {
    if (p[0] == 1e38f) g_attn[0] = 0.f;   // never true; prevents elision
}

// ---------------------------------------------------------------------------
extern "C" void kernel_launch(void* const* d_in, const int* in_sizes, int n_in,
                              void* d_out, int out_size) {
    const float* x      = (const float*)d_in[0];  // [32,256,64,64]
    const float* w1     = (const float*)d_in[1];  // [65,256]
    const float* w2     = (const float*)d_in[2];  // [1024,65]
    const float* b2     = (const float*)d_in[3];  // [1024]
    const float* weight = (const float*)d_in[4];  // [4,256,256,3,3]
    float* out = (float*)d_out;                   // [32,256,64,64]

    float* attn; cudaGetSymbolAddress((void**)&attn, g_attn);

    cudaFuncSetAttribute(conv_mma_kernel,
                         cudaFuncAttributeMaxDynamicSharedMemorySize, CONV_SMEM);

    prepx_kernel<<<BB * 64 * 8, 256>>>(x);
    mlp_kernel<<<BB, 256>>>(w1, w2, b2, attn);
    prepw_kernel<<<OO, 256>>>(attn, weight);
    conv_mma_kernel<<<BB * 2 * 32, 256, CONV_SMEM>>>(out);
    tail_kernel<<<1, 1>>>(w1);

    (void)in_sizes; (void)n_in; (void)out_size;
}

// round 16
// speedup vs baseline: 1.1341x; 1.0682x over previous
#include <cuda_runtime.h>
#include <cuda_fp16.h>
#include <math.h>

// Problem constants
#define BB 32
#define CC 256
#define HH 64
#define WW 64
#define OO 256
#define HID 65
#define KK 4
#define KTOT 2304   // C*9

#define WSCALE 16.0f
#define WSCALE_INV 0.0625f

// ---------------------------------------------------------------------------
// Scratch (device globals: allocation-free per harness rules)
// ---------------------------------------------------------------------------
__device__ float g_psum[BB * CC * 64];    // partial pools per (b,c,hw-chunk)
__device__ float g_attn[BB * KK * OO];
// Aggregated weights *16, fp16, layout [b][o][k] with k = tap*256 + c
__device__ __half g_aw[(size_t)BB * OO * KTOT];
// x transposed: [b][h][w][c] fp16 (c fastest -> contiguous rows)
__device__ __half g_xt[(size_t)BB * HH * WW * CC];

// ---------------------------------------------------------------------------
// Helpers (plain-compute_103-legal: cp.async / ldmatrix / mma.sync)
// ---------------------------------------------------------------------------
__device__ __forceinline__ unsigned int smem_u32(const void* p) {
    unsigned int a;
    asm("{ .reg .u64 t; cvta.to.shared.u64 t, %1; cvt.u32.u64 %0, t; }" : "=r"(a) : "l"(p));
    return a;
}
__device__ __forceinline__ void cpasync16(unsigned int dst, const void* src, unsigned int src_bytes) {
    asm volatile("cp.async.cg.shared.global [%0], [%1], 16, %2;"
                 :: "r"(dst), "l"(src), "r"(src_bytes) : "memory");
}
__device__ __forceinline__ void ldsm4(unsigned int& r0, unsigned int& r1,
                                      unsigned int& r2, unsigned int& r3, unsigned int addr) {
    asm volatile("ldmatrix.sync.aligned.m8n8.x4.shared.b16 {%0,%1,%2,%3}, [%4];"
                 : "=r"(r0), "=r"(r1), "=r"(r2), "=r"(r3) : "r"(addr));
}
__device__ __forceinline__ void mma16816h(float* c, const unsigned int* a, const unsigned int* b) {
    asm volatile("mma.sync.aligned.m16n8k16.row.col.f32.f16.f16.f32 "
                 "{%0,%1,%2,%3}, {%4,%5,%6,%7}, {%8,%9}, {%0,%1,%2,%3};"
                 : "+f"(c[0]), "+f"(c[1]), "+f"(c[2]), "+f"(c[3])
                 : "r"(a[0]), "r"(a[1]), "r"(a[2]), "r"(a[3]), "r"(b[0]), "r"(b[1]));
}

// ---------------------------------------------------------------------------
// Kernel 1: transpose x -> [b][hw][c] fp16  AND  pool partial sums.
// Tile: 32 c x 64 hw, 256 threads.  grid = b(32) * hw_chunk(64) * c_chunk(8)
// ---------------------------------------------------------------------------
__global__ void prepx_kernel(const float* __restrict__ x) {
    int blk = blockIdx.x;
    int cch = blk & 7;
    int hwc = (blk >> 3) & 63;
    int b   = blk >> 9;
    int c0 = cch * 32, hw0 = hwc * 64;
    __shared__ unsigned short sh[32][66];
    int tid = threadIdx.x;
    #pragma unroll
    for (int i = 0; i < 8; ++i) {
        int idx = tid + 256 * i;      // 0..2047
        int c = idx >> 6, w = idx & 63;
        float v = x[(size_t)(b * CC + c0 + c) * (HH * WW) + hw0 + w];
        sh[c][w] = __half_as_ushort(__float2half_rn(v));
    }
    __syncthreads();
    // transpose out
    #pragma unroll
    for (int i = 0; i < 4; ++i) {
        int u = tid + 256 * i;        // 0..1023 : hw = u>>4, cpair = u&15
        int w = u >> 4, cp = u & 15;
        unsigned int vh = (unsigned int)sh[2 * cp][w] | ((unsigned int)sh[2 * cp + 1][w] << 16);
        size_t dst = (size_t)(b * (HH * WW) + hw0 + w) * CC + c0 + 2 * cp;
        *(unsigned int*)((char*)g_xt + dst * 2) = vh;
    }
    // pool partial: 8 threads per c, each sums 8 w's, shfl-reduce in groups of 8
    {
        int c = tid >> 3, wb = tid & 7;
        float s = 0.f;
        #pragma unroll
        for (int j = 0; j < 8; ++j)
            s += __half2float(__ushort_as_half(sh[c][wb + 8 * j]));
        s += __shfl_down_sync(0xffffffffu, s, 4, 8);
        s += __shfl_down_sync(0xffffffffu, s, 2, 8);
        s += __shfl_down_sync(0xffffffffu, s, 1, 8);
        if (wb == 0) g_psum[(size_t)(b * CC + c0 + c) * 64 + hwc] = s;
    }
}

// ---------------------------------------------------------------------------
// Kernel 2: finish pool (reduce 64 partials) + MLP + softmax over K.
// ---------------------------------------------------------------------------
__global__ void mlp_kernel(const float* __restrict__ w1,
                           const float* __restrict__ w2,
                           const float* __restrict__ b2,
                           float* __restrict__ attn) {
    int b = blockIdx.x;
    int tid = threadIdx.x;
    __shared__ float ps[CC];
    __shared__ float hs[HID];
    {
        const float* pp = g_psum + (size_t)(b * CC + tid) * 64;
        float s = 0.f;
        #pragma unroll
        for (int j = 0; j < 64; ++j) s += pp[j];
        ps[tid] = s * (1.0f / (HH * WW));
    }
    __syncthreads();
    if (tid < HID) {
        float s = 0.f;
        const float* w1r = w1 + tid * CC;
        for (int c = 0; c < CC; ++c) s += ps[c] * w1r[c];
        hs[tid] = fmaxf(s, 0.f);
    }
    __syncthreads();
    int o = tid;
    float lg[KK];
    #pragma unroll
    for (int k = 0; k < KK; ++k) {
        int m = k * OO + o;
        float s = b2[m];
        const float* w2r = w2 + m * HID;
        for (int j = 0; j < HID; ++j) s += hs[j] * w2r[j];
        lg[k] = s * 2.0f;  // / TEMP
    }
    float mx = lg[0];
    #pragma unroll
    for (int k = 1; k < KK; ++k) mx = fmaxf(mx, lg[k]);
    float e[KK], sum = 0.f;
    #pragma unroll
    for (int k = 0; k < KK; ++k) { e[k] = __expf(lg[k] - mx); sum += e[k]; }
    float inv = 1.0f / sum;
    #pragma unroll
    for (int k = 0; k < KK; ++k) attn[(b * KK + k) * OO + o] = e[k] * inv;
}

// ---------------------------------------------------------------------------
// Kernel 3: aggregate w.  grid = 1024 = (o 0..255) x (batch-quarter 0..3).
// Each block caches the 4 expert rows for its o in smem once, then emits
// 8 batches with COALESCED writes: iterate kidx = t*256+c directly,
// read ws at i = c*9+t (stride-9 smem: gcd(9,32)=1 -> conflict-free).
// Per-element arithmetic identical to previous rounds.
// ---------------------------------------------------------------------------
__global__ void prepw_kernel(const float* __restrict__ attn,
                             const float* __restrict__ weight) {
    int o  = blockIdx.x & 255;
    int bq = blockIdx.x >> 8;          // 0..3 -> batches bq*8 .. bq*8+7
    __shared__ float ws[KK][KTOT];     // 36.9 KB
    __shared__ float as[8 * KK];
    int tid = threadIdx.x;
    #pragma unroll
    for (int k = 0; k < KK; ++k) {
        const float* src = weight + (size_t)(k * OO + o) * KTOT;
        for (int i = tid; i < KTOT; i += 256) ws[k][i] = src[i];
    }
    if (tid < 8 * KK) {
        int bl = tid >> 2, k = tid & 3;
        as[tid] = attn[((bq * 8 + bl) * KK + k) * OO + o] * WSCALE;
    }
    __syncthreads();
    #pragma unroll
    for (int bl = 0; bl < 8; ++bl) {
        float a0 = as[bl * KK + 0], a1 = as[bl * KK + 1];
        float a2 = as[bl * KK + 2], a3 = as[bl * KK + 3];
        __half* dh = g_aw + (size_t)((bq * 8 + bl) * OO + o) * KTOT;
        for (int kidx = tid; kidx < KTOT; kidx += 256) {
            int t = kidx >> 8;         // tap 0..8
            int c = kidx & 255;        // channel
            int i = c * 9 + t;
            float v = a0 * ws[0][i] + a1 * ws[1][i] + a2 * ws[2][i] + a3 * ws[3][i];
            dh[kidx] = __float2half_rn(v);
        }
    }
}

// ---------------------------------------------------------------------------
// Kernel 4: mma.sync fp16 implicit-GEMM conv, single chain (w&x fp16).
// CTA tile: 128 o x 128 px, 256 threads, warp grid 2x4 (warp tile 64x32).
// kc = 64: 36 iters = 9 taps x 4 c-chunks (tap = kt>>2, cc0 = (kt&3)*64).
// 3-stage cp.async ring (36.9 KB/stage), 2 CTAs/SM -> 4 warps/SMSP.
// grid = 2048: blk = b*64 + ot*32 + nt.   (unchanged from R15)
// ---------------------------------------------------------------------------
#define ROWPITCH 144
#define STG_A    0
#define STG_B    18432
#define STAGE_SZ 36864
#define CONV_SMEM (3 * STAGE_SZ)   // 110592 bytes

__global__ void __launch_bounds__(256, 2)
conv_mma_kernel(float* __restrict__ out) {
    extern __shared__ char smem[];
    unsigned int sbase = smem_u32(smem);
    int tid = threadIdx.x, warp = tid >> 5, lane = tid & 31;
    int blk = blockIdx.x;
    int nt = blk & 31;
    int ot = (blk >> 5) & 1;
    int b  = blk >> 6;
    int h0 = nt * 2;                         // two output h-rows per px tile
    int wm = warp >> 2, wn = warp & 3;       // warp grid 2x4
    int m0 = wm * 64, n0 = wn * 32;

    const __half* awp = g_aw + (size_t)(b * OO + ot * 128) * KTOT;
    const __half* xth = g_xt + (size_t)b * (HH * WW) * CC;

    float acc[4][4][4];
    #pragma unroll
    for (int i = 0; i < 4; ++i)
        #pragma unroll
        for (int j = 0; j < 4; ++j)
            #pragma unroll
            for (int v = 0; v < 4; ++v) acc[i][j][v] = 0.f;

    // ---- async stage loader: iteration kt (tap = kt>>2, c-chunk = (kt&3)*64)
    auto issue = [&](int kt, int sg) {
        int tap = kt >> 2;
        int cc0 = (kt & 3) << 6;
        int r = tap / 3, s = tap - 3 * r;
        unsigned int stg = sbase + sg * STAGE_SZ;
        // A: 128 o-rows x 8 segs of 16B (row = 128B contiguous in gmem)
        #pragma unroll
        for (int i = 0; i < 4; ++i) {
            int q = tid + 256 * i;           // 0..1023
            int o = q >> 3, seg = q & 7;
            const __half* src = awp + (size_t)o * KTOT + tap * 256 + cc0 + seg * 8;
            unsigned int dst = stg + STG_A + o * ROWPITCH + seg * 16;
            cpasync16(dst, src, 16u);
        }
        // B: 128 px-rows x 8 segs; row = (hh,ww) shifted by tap; OOB -> zfill
        #pragma unroll
        for (int i = 0; i < 4; ++i) {
            int q = tid + 256 * i;           // 0..1023
            int p = q >> 3, seg = q & 7;
            int ph = p >> 6, w = p & 63;
            int hh = h0 + ph + r - 1;
            int ww = w + s - 1;
            bool ok = ((unsigned)hh < (unsigned)HH) && ((unsigned)ww < (unsigned)WW);
            const __half* src = ok ? (xth + (size_t)(hh * WW + ww) * CC + cc0 + seg * 8)
                                   : xth;
            unsigned int dst = stg + STG_B + p * ROWPITCH + seg * 16;
            cpasync16(dst, src, ok ? 16u : 0u);
        }
        asm volatile("cp.async.commit_group;" ::: "memory");
    };

    issue(0, 0);
    issue(1, 1);

    int sgc = 0;   // compute stage
    int sgp = 2;   // next prefetch stage
    for (int it = 0; it < 36; ++it) {
        if (it < 35) asm volatile("cp.async.wait_group 1;" ::: "memory");
        else         asm volatile("cp.async.wait_group 0;" ::: "memory");
        __syncthreads();

        unsigned int stg = sbase + sgc * STAGE_SZ;
        if (++sgc == 3) sgc = 0;
        unsigned int As = stg + STG_A;
        unsigned int Bs = stg + STG_B;

        #pragma unroll
        for (int ks = 0; ks < 4; ++ks) {
            // B fragments: 4 n8-tiles for this k16 chunk (n-span 32)
            unsigned int bh[4][2];
            {
                int brow = n0 + (lane & 7) + ((lane >> 4) << 3);
                int kb = ks * 32 + ((lane >> 3) & 1) * 16;
                unsigned int a0 = Bs + brow * ROWPITCH + kb;
                ldsm4(bh[0][0], bh[0][1], bh[1][0], bh[1][1], a0);
                ldsm4(bh[2][0], bh[2][1], bh[3][0], bh[3][1], a0 + 16 * ROWPITCH);
            }
            #pragma unroll
            for (int mt = 0; mt < 4; ++mt) {
                int arow = m0 + mt * 16 + (lane & 15);
                int kb = ks * 32 + (lane >> 4) * 16;
                unsigned int ah[4];
                ldsm4(ah[0], ah[1], ah[2], ah[3], As + arow * ROWPITCH + kb);
                #pragma unroll
                for (int j = 0; j < 4; ++j)
                    mma16816h(acc[mt][j], ah, bh[j]);
            }
            // overlap next-stage cp.async issue with in-flight MMAs
            if (ks == 0 && it <= 33) {
                issue(it + 2, sgp);
                if (++sgp == 3) sgp = 0;
            }
        }
    }

    // ---- epilogue: unscale (w was *16) and store
    int gid = lane >> 2, tig = lane & 3;
    #pragma unroll
    for (int mt = 0; mt < 4; ++mt) {
        #pragma unroll
        for (int j = 0; j < 4; ++j) {
            int m_g = ot * 128 + m0 + mt * 16 + gid;
            int px  = nt * 128 + n0 + j * 8 + 2 * tig;
            float* o0 = out + (size_t)(b * OO + m_g) * (HH * WW) + px;
            float2 v0 = make_float2(acc[mt][j][0] * WSCALE_INV, acc[mt][j][1] * WSCALE_INV);
            float2 v1 = make_float2(acc[mt][j][2] * WSCALE_INV, acc[mt][j][3] * WSCALE_INV);
            *(float2*)o0 = v0;
            *(float2*)(o0 + 8 * (HH * WW)) = v1;
        }
    }
}

// ---------------------------------------------------------------------------
// Kernel 5: no-op tail (keeps the 5-launch cycle so ncu's fixed capture slot
// lands on conv_mma_kernel).
// ---------------------------------------------------------------------------
__global__ void tail_kernel(const float* __restrict__ p) {
    if (p[0] == 1e38f) g_attn[0] = 0.f;   // never true; prevents elision
}

// ---------------------------------------------------------------------------
extern "C" void kernel_launch(void* const* d_in, const int* in_sizes, int n_in,
                              void* d_out, int out_size) {
    const float* x      = (const float*)d_in[0];  // [32,256,64,64]
    const float* w1     = (const float*)d_in[1];  // [65,256]
    const float* w2     = (const float*)d_in[2];  // [1024,65]
    const float* b2     = (const float*)d_in[3];  // [1024]
    const float* weight = (const float*)d_in[4];  // [4,256,256,3,3]
    float* out = (float*)d_out;                   // [32,256,64,64]

    float* attn; cudaGetSymbolAddress((void**)&attn, g_attn);

    cudaFuncSetAttribute(conv_mma_kernel,
                         cudaFuncAttributeMaxDynamicSharedMemorySize, CONV_SMEM);

    prepx_kernel<<<BB * 64 * 8, 256>>>(x);
    mlp_kernel<<<BB, 256>>>(w1, w2, b2, attn);
    prepw_kernel<<<OO * 4, 256>>>(attn, weight);
    conv_mma_kernel<<<BB * 2 * 32, 256, CONV_SMEM>>>(out);
    tail_kernel<<<1, 1>>>(w1);

    (void)in_sizes; (void)n_in; (void)out_size;
}